// round 2
// baseline (speedup 1.0000x reference)
#include <cuda_runtime.h>

// Problem constants (fixed shapes from reference)
#define NQc 8192
#define NKc 8192
#define Dc  512

__device__ __align__(16) float g_Qp[(size_t)NQc * Dc];
__device__ __align__(16) float g_Kp[(size_t)NKc * Dc];
__device__ __align__(16) float g_S [(size_t)NQc * NKc];

static constexpr float SCALE_P = 0.044194173824159216f; // 1/sqrt(512)
static constexpr float NEGV    = -4294967296.0f;        // -(1<<32)

enum { EPI_NONE = 0, EPI_BIAS = 1, EPI_MASK = 2 };

// C[M,N] = A[M,K] @ op(B) where op(B)=B^T if BT (B is [N,K]) else B (B is [K,N]).
// EPI_BIAS: += bias[col].  EPI_MASK: c = mask[row*N+col] ? NEGV : c*SCALE_P.
// mask is int32 (harness materializes numpy bool as int32).
// Requires: M%128==0, N%64==0, K%16==0.
template <bool BT, int EPI>
__global__ __launch_bounds__(256)
void sgemm_kernel(const float* __restrict__ A, const float* __restrict__ B,
                  float* __restrict__ C, const float* __restrict__ bias,
                  const int* __restrict__ mask,
                  int M, int N, int K)
{
    constexpr int BM = 128, BN = 64, BK = 16;
    constexpr int AST = 132;  // 132*4 = 528 = 33*16 -> float4-aligned rows
    constexpr int BST = 68;   // 68*4  = 272 = 17*16 -> float4-aligned rows

    __shared__ __align__(16) float As[BK][AST];
    __shared__ __align__(16) float Bs[BK][BST];

    const int t  = threadIdx.x;
    const int tx = t & 15;        // 16 -> covers BN via tx*4
    const int ty = t >> 4;        // 16 -> covers BM via ty*8
    const int rowBase = blockIdx.y * BM;
    const int colBase = blockIdx.x * BN;

    float acc[8][4];
#pragma unroll
    for (int i = 0; i < 8; i++)
#pragma unroll
        for (int j = 0; j < 4; j++) acc[i][j] = 0.0f;

    for (int k0 = 0; k0 < K; k0 += BK) {
        // ---- load A tile [BM x BK], store transposed As[k][m]
#pragma unroll
        for (int l = 0; l < 2; l++) {
            int f = t + l * 256;           // 512 float4s total
            int r = f >> 2, q = f & 3;
            const float4 v = *(const float4*)(A + (size_t)(rowBase + r) * K + k0 + q * 4);
            As[q * 4 + 0][r] = v.x;
            As[q * 4 + 1][r] = v.y;
            As[q * 4 + 2][r] = v.z;
            As[q * 4 + 3][r] = v.w;
        }
        // ---- load B tile
        if (BT) {
            // B is [N,K]: tile rows = output cols; store transposed Bs[k][n]
            int n = t >> 2, q = t & 3;     // 256 float4s
            const float4 v = *(const float4*)(B + (size_t)(colBase + n) * K + k0 + q * 4);
            Bs[q * 4 + 0][n] = v.x;
            Bs[q * 4 + 1][n] = v.y;
            Bs[q * 4 + 2][n] = v.z;
            Bs[q * 4 + 3][n] = v.w;
        } else {
            // B is [K,N]: direct copy Bs[k][n]
            int kr = t >> 4, nq = t & 15;  // 16 x 16 float4s
            const float4 v = *(const float4*)(B + (size_t)(k0 + kr) * N + colBase + nq * 4);
            *(float4*)&Bs[kr][nq * 4] = v;
        }
        __syncthreads();

#pragma unroll
        for (int k = 0; k < BK; k++) {
            const float4 a0 = *(const float4*)&As[k][ty * 8];
            const float4 a1 = *(const float4*)&As[k][ty * 8 + 4];
            const float4 bv = *(const float4*)&Bs[k][tx * 4];
            const float a[8] = {a0.x, a0.y, a0.z, a0.w, a1.x, a1.y, a1.z, a1.w};
            const float b[4] = {bv.x, bv.y, bv.z, bv.w};
#pragma unroll
            for (int i = 0; i < 8; i++)
#pragma unroll
                for (int j = 0; j < 4; j++) acc[i][j] += a[i] * b[j];
        }
        __syncthreads();
    }

    // ---- epilogue + store
    const int col = colBase + tx * 4;
    float4 bv4 = make_float4(0.f, 0.f, 0.f, 0.f);
    if (EPI == EPI_BIAS) bv4 = *(const float4*)(bias + col);

#pragma unroll
    for (int i = 0; i < 8; i++) {
        const int row = rowBase + ty * 8 + i;
        float4 o = make_float4(acc[i][0], acc[i][1], acc[i][2], acc[i][3]);
        if (EPI == EPI_BIAS) {
            o.x += bv4.x; o.y += bv4.y; o.z += bv4.z; o.w += bv4.w;
        } else if (EPI == EPI_MASK) {
            const int4 m = *(const int4*)(mask + (size_t)row * N + col);
            o.x = m.x ? NEGV : o.x * SCALE_P;
            o.y = m.y ? NEGV : o.y * SCALE_P;
            o.z = m.z ? NEGV : o.z * SCALE_P;
            o.w = m.w ? NEGV : o.w * SCALE_P;
        }
        *(float4*)(C + (size_t)row * N + col) = o;
    }
}

// In-place row softmax over NKc columns. One block per row, 256 threads, 32 elems/thread.
__global__ __launch_bounds__(256)
void softmax_kernel(float* __restrict__ S)
{
    __shared__ float red[256];
    const int row = blockIdx.x;
    const int t = threadIdx.x;
    float* p = S + (size_t)row * NKc;

    float v[32];
    float mx = -3.4e38f;
#pragma unroll
    for (int i = 0; i < 32; i++) {
        v[i] = p[i * 256 + t];
        mx = fmaxf(mx, v[i]);
    }
    red[t] = mx;
    __syncthreads();
    for (int s = 128; s > 0; s >>= 1) {
        if (t < s) red[t] = fmaxf(red[t], red[t + s]);
        __syncthreads();
    }
    mx = red[0];
    __syncthreads();

    float sum = 0.0f;
#pragma unroll
    for (int i = 0; i < 32; i++) {
        v[i] = expf(v[i] - mx);
        sum += v[i];
    }
    red[t] = sum;
    __syncthreads();
    for (int s = 128; s > 0; s >>= 1) {
        if (t < s) red[t] += red[t + s];
        __syncthreads();
    }
    const float inv = 1.0f / red[0];
#pragma unroll
    for (int i = 0; i < 32; i++) p[i * 256 + t] = v[i] * inv;
}

extern "C" void kernel_launch(void* const* d_in, const int* in_sizes, int n_in,
                              void* d_out, int out_size)
{
    (void)in_sizes; (void)n_in; (void)out_size;
    const float* Q   = (const float*)d_in[0];
    const float* K   = (const float*)d_in[1];
    const float* V   = (const float*)d_in[2];
    const float* WQw = (const float*)d_in[3];
    const float* WQb = (const float*)d_in[4];
    const float* WKw = (const float*)d_in[5];
    const float* WKb = (const float*)d_in[6];
    const int*   mask = (const int*)d_in[7]; // numpy bool -> int32 on device
    float* O = (float*)d_out;

    float *Qp, *Kp, *S;
    cudaGetSymbolAddress((void**)&Qp, g_Qp);
    cudaGetSymbolAddress((void**)&Kp, g_Kp);
    cudaGetSymbolAddress((void**)&S,  g_S);

    const dim3 blk(256);

    // 1) Projections: Qp = Q @ WQw^T + WQb ; Kp = K @ WKw^T + WKb   [8192 x 512]
    {
        dim3 grid(Dc / 64, NQc / 128);
        sgemm_kernel<true, EPI_BIAS><<<grid, blk>>>(Q, WQw, Qp, WQb, nullptr, NQc, Dc, Dc);
        sgemm_kernel<true, EPI_BIAS><<<grid, blk>>>(K, WKw, Kp, WKb, nullptr, NKc, Dc, Dc);
    }

    // 2) S = mask ? NEG : (Qp @ Kp^T) * (1/sqrt(512))   [8192 x 8192]
    {
        dim3 grid(NKc / 64, NQc / 128);
        sgemm_kernel<true, EPI_MASK><<<grid, blk>>>(Qp, Kp, S, nullptr, mask, NQc, NKc, Dc);
    }

    // 3) P = softmax_rows(S), in place
    softmax_kernel<<<NQc, blk>>>(S);

    // 4) O = P @ V   [8192 x 512]
    {
        dim3 grid(Dc / 64, NQc / 128);
        sgemm_kernel<false, EPI_NONE><<<grid, blk>>>(S, V, O, nullptr, nullptr, NQc, Dc, NKc);
    }
}

// round 5
// speedup vs baseline: 2.0419x; 2.0419x over previous
#include <cuda_runtime.h>
#include <cstdint>

// Problem constants (fixed shapes from reference)
#define NQc 8192
#define NKc 8192
#define Dc  512

__device__ __align__(16) float g_Qp[(size_t)NQc * Dc];
__device__ __align__(16) float g_Kp[(size_t)NKc * Dc];
__device__ __align__(16) float g_Vt[(size_t)Dc * NKc];
__device__ __align__(16) float g_S [(size_t)NQc * NKc];

static constexpr float SCALE_P = 0.044194173824159216f; // 1/sqrt(512)
static constexpr float NEGV    = -4294967296.0f;        // -(1<<32)

enum { EPI_NONE = 0, EPI_BIAS = 1, EPI_MASK = 2 };

// fp32 -> tf32 (round-to-nearest) kept in a 32-bit container
__device__ __forceinline__ uint32_t f2tf(float f) {
    uint32_t r;
    asm("cvt.rna.tf32.f32 %0, %1;" : "=r"(r) : "f"(f));
    return r;
}

__device__ __forceinline__ void mma8(float* c, const uint32_t* a, const uint32_t* b) {
    asm volatile(
        "mma.sync.aligned.m16n8k8.row.col.f32.tf32.tf32.f32 "
        "{%0,%1,%2,%3}, {%4,%5,%6,%7}, {%8,%9}, {%0,%1,%2,%3};"
        : "+f"(c[0]), "+f"(c[1]), "+f"(c[2]), "+f"(c[3])
        : "r"(a[0]), "r"(a[1]), "r"(a[2]), "r"(a[3]), "r"(b[0]), "r"(b[1]));
}

// ---------------------------------------------------------------- mma GEMM
// C[M,N] = A[M,K] @ B^T, A:[M,K], B:[N,K], all K-major.
// BM=128, BN=128, BK=32; 256 threads = 8 warps (2 M x 4 N), warp tile 64x32.
// Smem tiles stored [row][32] with XOR swizzle col4' = col4 ^ (row&7):
//   - loader STS.128 conflict-free, fragment LDS.32 conflict-free.
// Requires M%128==0, N%128==0, K%32==0.
template <int EPI>
__global__ void __launch_bounds__(256)
mma_gemm(const float* __restrict__ A, const float* __restrict__ B,
         float* __restrict__ C, const float* __restrict__ bias,
         const int* __restrict__ mask, int M, int N, int K)
{
    constexpr int BM = 128, BN = 128, BK = 32;
    constexpr int STAGE = (BM + BN) * BK;     // floats per stage (8192)

    extern __shared__ float sm[];

    const int tid  = threadIdx.x;
    const int lane = tid & 31;
    const int wid  = tid >> 5;
    const int g    = lane >> 2;     // group id 0..7
    const int t    = lane & 3;      // thread-in-group 0..3

    const int warpM = wid & 1;          // 2 warps in M
    const int warpN = wid >> 1;         // 4 warps in N
    const int m_warp = warpM * 64;
    const int n_warp = warpN * 32;

    const int rowBase = blockIdx.y * BM;
    const int colBase = blockIdx.x * BN;

    // loader mapping: r = (tid>>3) + 32*it, q = tid&7  (coalesced LDG.128)
    const int lr = tid >> 3;
    const int lq = tid & 7;
    const int sq = lq ^ (lr & 7);       // swizzled float4 column (same for all it: (lr+32it)&7 == lr&7)

    const float* pa = A + (size_t)(rowBase + lr) * K + lq * 4;
    const float* pb = B + (size_t)(colBase + lr) * K + lq * 4;

    float acc[4][4][4];
#pragma unroll
    for (int i = 0; i < 4; i++)
#pragma unroll
        for (int j = 0; j < 4; j++)
#pragma unroll
            for (int r = 0; r < 4; r++) acc[i][j][r] = 0.0f;

    const int KC = K / BK;
    uint4 ra[4], rb[4];

    // ---- prefetch chunk 0
#pragma unroll
    for (int it = 0; it < 4; it++) {
        const float4 va = *(const float4*)(pa + (size_t)(32 * it) * K);
        const float4 vb = *(const float4*)(pb + (size_t)(32 * it) * K);
        ra[it] = make_uint4(f2tf(va.x), f2tf(va.y), f2tf(va.z), f2tf(va.w));
        rb[it] = make_uint4(f2tf(vb.x), f2tf(vb.y), f2tf(vb.z), f2tf(vb.w));
    }
    {
        float* as0 = sm;
        float* bs0 = sm + BM * BK;
#pragma unroll
        for (int it = 0; it < 4; it++) {
            *(uint4*)(as0 + (lr + 32 * it) * BK + 4 * sq) = ra[it];
            *(uint4*)(bs0 + (lr + 32 * it) * BK + 4 * sq) = rb[it];
        }
    }
    __syncthreads();

    for (int c = 0; c < KC; c++) {
        // ---- issue LDG for chunk c+1 (latency hidden under MMA below)
        if (c + 1 < KC) {
            const float* qa = pa + (size_t)(c + 1) * BK;
            const float* qb = pb + (size_t)(c + 1) * BK;
#pragma unroll
            for (int it = 0; it < 4; it++) {
                const float4 va = *(const float4*)(qa + (size_t)(32 * it) * K);
                const float4 vb = *(const float4*)(qb + (size_t)(32 * it) * K);
                ra[it] = make_uint4(f2tf(va.x), f2tf(va.y), f2tf(va.z), f2tf(va.w));
                rb[it] = make_uint4(f2tf(vb.x), f2tf(vb.y), f2tf(vb.z), f2tf(vb.w));
            }
        }

        // ---- MMA over stage c&1
        const float* as_ = sm + (c & 1) * STAGE;
        const float* bs_ = as_ + BM * BK;
#pragma unroll
        for (int ks = 0; ks < 4; ks++) {
            const int k0 = ks * 8;
            uint32_t af[4][4];
#pragma unroll
            for (int mi = 0; mi < 4; mi++) {
                const int r0 = m_warp + 16 * mi + g;
                const int r1 = r0 + 8;
                const int x0 = 4 * (r0 & 7), x1 = 4 * (r1 & 7);
                af[mi][0] = __float_as_uint(as_[r0 * BK + ((k0 + t) ^ x0)]);
                af[mi][1] = __float_as_uint(as_[r1 * BK + ((k0 + t) ^ x1)]);
                af[mi][2] = __float_as_uint(as_[r0 * BK + ((k0 + t + 4) ^ x0)]);
                af[mi][3] = __float_as_uint(as_[r1 * BK + ((k0 + t + 4) ^ x1)]);
            }
            uint32_t bf[4][2];
#pragma unroll
            for (int nj = 0; nj < 4; nj++) {
                const int n0 = n_warp + 8 * nj + g;
                const int x = 4 * (n0 & 7);
                bf[nj][0] = __float_as_uint(bs_[n0 * BK + ((k0 + t) ^ x)]);
                bf[nj][1] = __float_as_uint(bs_[n0 * BK + ((k0 + t + 4) ^ x)]);
            }
#pragma unroll
            for (int mi = 0; mi < 4; mi++)
#pragma unroll
                for (int nj = 0; nj < 4; nj++)
                    mma8(acc[mi][nj], af[mi], bf[nj]);
        }

        // ---- store chunk c+1 into other stage
        if (c + 1 < KC) {
            float* as1 = sm + ((c + 1) & 1) * STAGE;
            float* bs1 = as1 + BM * BK;
#pragma unroll
            for (int it = 0; it < 4; it++) {
                *(uint4*)(as1 + (lr + 32 * it) * BK + 4 * sq) = ra[it];
                *(uint4*)(bs1 + (lr + 32 * it) * BK + 4 * sq) = rb[it];
            }
            __syncthreads();
        }
    }

    // ---- epilogue
    const int colW = colBase + n_warp;
#pragma unroll
    for (int mi = 0; mi < 4; mi++) {
        const int row0 = rowBase + m_warp + 16 * mi + g;
#pragma unroll
        for (int rr = 0; rr < 2; rr++) {
            const int row = row0 + 8 * rr;
            float* crow = C + (size_t)row * N;
            const int* mrow = (EPI == EPI_MASK) ? (mask + (size_t)row * N) : nullptr;
#pragma unroll
            for (int nj = 0; nj < 4; nj++) {
                const int col = colW + 8 * nj + 2 * t;
                float2 o = make_float2(acc[mi][nj][2 * rr], acc[mi][nj][2 * rr + 1]);
                if (EPI == EPI_BIAS) {
                    const float2 b = *(const float2*)(bias + col);
                    o.x += b.x; o.y += b.y;
                } else if (EPI == EPI_MASK) {
                    const int2 m = *(const int2*)(mrow + col);
                    o.x = m.x ? NEGV : o.x * SCALE_P;
                    o.y = m.y ? NEGV : o.y * SCALE_P;
                }
                *(float2*)(crow + col) = o;
            }
        }
    }
}

static constexpr int GEMM_SMEM = 2 * (128 + 128) * 32 * 4;  // 65536 bytes

// ---------------------------------------------------------------- V transpose
// Vt[d][n] = V[n][d];  V:[NKc][Dc] -> Vt:[Dc][NKc]
__global__ __launch_bounds__(256)
void transpose_kernel(const float* __restrict__ V, float* __restrict__ Vt)
{
    __shared__ float tile[32][33];
    const int d0 = blockIdx.x * 32;
    const int n0 = blockIdx.y * 32;
    const int tx = threadIdx.x, ty = threadIdx.y;
#pragma unroll
    for (int j = 0; j < 32; j += 8)
        tile[ty + j][tx] = V[(size_t)(n0 + ty + j) * Dc + d0 + tx];
    __syncthreads();
#pragma unroll
    for (int j = 0; j < 32; j += 8)
        Vt[(size_t)(d0 + ty + j) * NKc + n0 + tx] = tile[tx][ty + j];
}

// ---------------------------------------------------------------- softmax
__global__ __launch_bounds__(256)
void softmax_kernel(float* __restrict__ S)
{
    __shared__ float red[256];
    const int row = blockIdx.x;
    const int t = threadIdx.x;
    float* p = S + (size_t)row * NKc;

    float v[32];
    float mx = -3.4e38f;
#pragma unroll
    for (int i = 0; i < 32; i++) {
        v[i] = p[i * 256 + t];
        mx = fmaxf(mx, v[i]);
    }
    red[t] = mx;
    __syncthreads();
    for (int s = 128; s > 0; s >>= 1) {
        if (t < s) red[t] = fmaxf(red[t], red[t + s]);
        __syncthreads();
    }
    mx = red[0];
    __syncthreads();

    float sum = 0.0f;
#pragma unroll
    for (int i = 0; i < 32; i++) {
        v[i] = expf(v[i] - mx);
        sum += v[i];
    }
    red[t] = sum;
    __syncthreads();
    for (int s = 128; s > 0; s >>= 1) {
        if (t < s) red[t] += red[t + s];
        __syncthreads();
    }
    const float inv = 1.0f / red[0];
#pragma unroll
    for (int i = 0; i < 32; i++) p[i * 256 + t] = v[i] * inv;
}

// ---------------------------------------------------------------- launcher
extern "C" void kernel_launch(void* const* d_in, const int* in_sizes, int n_in,
                              void* d_out, int out_size)
{
    (void)in_sizes; (void)n_in; (void)out_size;
    const float* Q    = (const float*)d_in[0];
    const float* K    = (const float*)d_in[1];
    const float* V    = (const float*)d_in[2];
    const float* WQw  = (const float*)d_in[3];
    const float* WQb  = (const float*)d_in[4];
    const float* WKw  = (const float*)d_in[5];
    const float* WKb  = (const float*)d_in[6];
    const int*   mask = (const int*)d_in[7];  // numpy bool -> int32 on device
    float* O = (float*)d_out;

    float *Qp, *Kp, *Vt, *S;
    cudaGetSymbolAddress((void**)&Qp, g_Qp);
    cudaGetSymbolAddress((void**)&Kp, g_Kp);
    cudaGetSymbolAddress((void**)&Vt, g_Vt);
    cudaGetSymbolAddress((void**)&S,  g_S);

    cudaFuncSetAttribute(mma_gemm<EPI_BIAS>,
                         cudaFuncAttributeMaxDynamicSharedMemorySize, GEMM_SMEM);
    cudaFuncSetAttribute(mma_gemm<EPI_MASK>,
                         cudaFuncAttributeMaxDynamicSharedMemorySize, GEMM_SMEM);
    cudaFuncSetAttribute(mma_gemm<EPI_NONE>,
                         cudaFuncAttributeMaxDynamicSharedMemorySize, GEMM_SMEM);

    const dim3 blk(256);

    // 0) Vt = V^T   [512 x 8192]
    transpose_kernel<<<dim3(Dc / 32, NKc / 32), dim3(32, 8)>>>(V, Vt);

    // 1) Projections: Qp = Q @ WQw^T + WQb ; Kp = K @ WKw^T + WKb   [8192 x 512]
    {
        dim3 grid(Dc / 128, NQc / 128);
        mma_gemm<EPI_BIAS><<<grid, blk, GEMM_SMEM>>>(Q, WQw, Qp, WQb, nullptr, NQc, Dc, Dc);
        mma_gemm<EPI_BIAS><<<grid, blk, GEMM_SMEM>>>(K, WKw, Kp, WKb, nullptr, NKc, Dc, Dc);
    }
    // 2) S = mask ? NEG : (Qp @ Kp^T) * (1/sqrt(512))   [8192 x 8192]
    {
        dim3 grid(NKc / 128, NQc / 128);
        mma_gemm<EPI_MASK><<<grid, blk, GEMM_SMEM>>>(Qp, Kp, S, nullptr, mask, NQc, NKc, Dc);
    }
    // 3) P = softmax_rows(S), in place
    softmax_kernel<<<NQc, blk>>>(S);
    // 4) O = P @ V = P @ Vt^T   [8192 x 512]
    {
        dim3 grid(Dc / 128, NQc / 128);
        mma_gemm<EPI_NONE><<<grid, blk, GEMM_SMEM>>>(S, Vt, O, nullptr, nullptr, NQc, Dc, NKc);
    }
}

// round 6
// speedup vs baseline: 3.7804x; 1.8514x over previous
#include <cuda_runtime.h>
#include <cstdint>

// Problem constants (fixed shapes from reference)
#define NQc 8192
#define NKc 8192
#define Dc  512

__device__ __align__(16) float g_Qp[(size_t)NQc * Dc];
__device__ __align__(16) float g_Kp[(size_t)NKc * Dc];
__device__ __align__(16) float g_Vt[(size_t)Dc * NKc];
__device__ __align__(16) float g_S [(size_t)NQc * NKc];

static constexpr float SCALE_P = 0.044194173824159216f; // 1/sqrt(512)
static constexpr float NEGV    = -4294967296.0f;        // -(1<<32)

enum { EPI_NONE = 0, EPI_BIAS = 1, EPI_MASK = 2 };

// fp32 -> tf32 (round-to-nearest) kept in a 32-bit container (low 13 bits zero)
__device__ __forceinline__ uint32_t f2tf(float f) {
    uint32_t r;
    asm("cvt.rna.tf32.f32 %0, %1;" : "=r"(r) : "f"(f));
    return r;
}
__device__ __forceinline__ float f2tf_f(float f) { return __uint_as_float(f2tf(f)); }

__device__ __forceinline__ uint32_t smem_u32(const void* p) {
    uint32_t r;
    asm("{ .reg .u64 t; cvta.to.shared.u64 t, %1; cvt.u32.u64 %0, t; }"
        : "=r"(r) : "l"(p));
    return r;
}

#define CP_ASYNC16(dst, src) \
    asm volatile("cp.async.cg.shared.global [%0], [%1], 16;" \
                 :: "r"(dst), "l"(src) : "memory")
#define CP_COMMIT() asm volatile("cp.async.commit_group;" ::: "memory")
#define CP_WAIT(N)  asm volatile("cp.async.wait_group %0;" :: "n"(N) : "memory")

__device__ __forceinline__ void mma8(float* c, const uint32_t* a, const uint32_t* b) {
    asm volatile(
        "mma.sync.aligned.m16n8k8.row.col.f32.tf32.tf32.f32 "
        "{%0,%1,%2,%3}, {%4,%5,%6,%7}, {%8,%9}, {%0,%1,%2,%3};"
        : "+f"(c[0]), "+f"(c[1]), "+f"(c[2]), "+f"(c[3])
        : "r"(a[0]), "r"(a[1]), "r"(a[2]), "r"(a[3]), "r"(b[0]), "r"(b[1]));
}

// ---------------------------------------------------------------- mma GEMM
// C[M,N] = A[M,K] @ B^T, A:[M,K], B:[N,K], all K-major.
// BM=128, BN=128, BK=32; 256 threads = 8 warps (2 M x 4 N), warp tile 64x32.
// 3-stage cp.async pipeline. Smem tiles [row][32] with XOR swizzle on the
// float4 column (col4' = col4 ^ (row&7)): cp.async dst and LDS.32 fragment
// gathers are both conflict-free.
// NOTE: MMA reads raw fp32 bits as tf32 (truncation). For exact tf32 math,
// A/B must be pre-rounded to tf32 in gmem (true for Qp, Kp, P, Vt).
// Requires M%128==0, N%128==0, K%64==0 (KC>=2).
template <int EPI>
__global__ void __launch_bounds__(256, 2)
mma_gemm(const float* __restrict__ A, const float* __restrict__ B,
         float* __restrict__ C, const float* __restrict__ bias,
         const int* __restrict__ mask, int M, int N, int K)
{
    constexpr int BM = 128, BN = 128, BK = 32, STAGES = 3;
    constexpr int STAGE_F = (BM + BN) * BK;       // floats per stage (8192)
    constexpr int STAGE_B = STAGE_F * 4;          // bytes (32768)

    extern __shared__ float sm[];
    const uint32_t smb = smem_u32(sm);

    const int tid  = threadIdx.x;
    const int lane = tid & 31;
    const int wid  = tid >> 5;
    const int g    = lane >> 2;     // group id 0..7
    const int t    = lane & 3;      // thread-in-group 0..3

    const int m_warp = (wid & 1) * 64;   // 2 warps in M
    const int n_warp = (wid >> 1) * 32;  // 4 warps in N

    const int rowBase = blockIdx.y * BM;
    const int colBase = blockIdx.x * BN;

    // loader mapping: rows lr+32*it, float4 col lq, swizzled col sq
    const int lr = tid >> 3;
    const int lq = tid & 7;
    const int sq = lq ^ (lr & 7);

    const float* pa = A + (size_t)(rowBase + lr) * K + lq * 4;
    const float* pb = B + (size_t)(colBase + lr) * K + lq * 4;
    const uint32_t sa = smb + (uint32_t)(lr * BK + 4 * sq) * 4;
    const uint32_t sb = sa + (uint32_t)(BM * BK) * 4;

    const int KC = K / BK;

    // issue one stage of cp.async (8 x 16B per thread)
    auto issue = [&](int c, int s) {
        const float* qa = pa + (size_t)c * BK;
        const float* qb = pb + (size_t)c * BK;
        const uint32_t off = (uint32_t)s * STAGE_B;
#pragma unroll
        for (int it = 0; it < 4; it++) {
            CP_ASYNC16(sa + off + (uint32_t)(32 * it * BK) * 4, qa + (size_t)(32 * it) * K);
            CP_ASYNC16(sb + off + (uint32_t)(32 * it * BK) * 4, qb + (size_t)(32 * it) * K);
        }
        CP_COMMIT();
    };

    issue(0, 0);
    issue(1, 1);

    float acc[4][4][4];
#pragma unroll
    for (int i = 0; i < 4; i++)
#pragma unroll
        for (int j = 0; j < 4; j++)
#pragma unroll
            for (int r = 0; r < 4; r++) acc[i][j][r] = 0.0f;

    for (int c = 0; c < KC; c++) {
        if (c + 2 < KC) { CP_WAIT(1); } else { CP_WAIT(0); }
        __syncthreads();

        if (c + 2 < KC) issue(c + 2, (c + 2) % STAGES);

        const float* as_ = sm + (c % STAGES) * STAGE_F;
        const float* bs_ = as_ + BM * BK;
#pragma unroll
        for (int ks = 0; ks < 4; ks++) {
            const int k0 = ks * 8;
            uint32_t af[4][4];
#pragma unroll
            for (int mi = 0; mi < 4; mi++) {
                const int r0 = m_warp + 16 * mi + g;
                const int r1 = r0 + 8;
                const int x0 = 4 * (r0 & 7), x1 = 4 * (r1 & 7);
                af[mi][0] = __float_as_uint(as_[r0 * BK + ((k0 + t) ^ x0)]);
                af[mi][1] = __float_as_uint(as_[r1 * BK + ((k0 + t) ^ x1)]);
                af[mi][2] = __float_as_uint(as_[r0 * BK + ((k0 + t + 4) ^ x0)]);
                af[mi][3] = __float_as_uint(as_[r1 * BK + ((k0 + t + 4) ^ x1)]);
            }
            uint32_t bf[4][2];
#pragma unroll
            for (int nj = 0; nj < 4; nj++) {
                const int n0 = n_warp + 8 * nj + g;
                const int x = 4 * (n0 & 7);
                bf[nj][0] = __float_as_uint(bs_[n0 * BK + ((k0 + t) ^ x)]);
                bf[nj][1] = __float_as_uint(bs_[n0 * BK + ((k0 + t + 4) ^ x)]);
            }
#pragma unroll
            for (int mi = 0; mi < 4; mi++)
#pragma unroll
                for (int nj = 0; nj < 4; nj++)
                    mma8(acc[mi][nj], af[mi], bf[nj]);
        }
        __syncthreads();
    }

    // ---- epilogue
    const int colW = colBase + n_warp;
#pragma unroll
    for (int mi = 0; mi < 4; mi++) {
        const int row0 = rowBase + m_warp + 16 * mi + g;
#pragma unroll
        for (int rr = 0; rr < 2; rr++) {
            const int row = row0 + 8 * rr;
            float* crow = C + (size_t)row * N;
            const int* mrow = (EPI == EPI_MASK) ? (mask + (size_t)row * N) : nullptr;
#pragma unroll
            for (int nj = 0; nj < 4; nj++) {
                const int col = colW + 8 * nj + 2 * t;
                float2 o = make_float2(acc[mi][nj][2 * rr], acc[mi][nj][2 * rr + 1]);
                if (EPI == EPI_BIAS) {
                    const float2 b = *(const float2*)(bias + col);
                    // round to tf32 so downstream cp.async GEMM is exact
                    o.x = f2tf_f(o.x + b.x);
                    o.y = f2tf_f(o.y + b.y);
                } else if (EPI == EPI_MASK) {
                    const int2 m = *(const int2*)(mrow + col);
                    o.x = m.x ? NEGV : o.x * SCALE_P;
                    o.y = m.y ? NEGV : o.y * SCALE_P;
                }
                *(float2*)(crow + col) = o;
            }
        }
    }
}

static constexpr int GEMM_SMEM = 3 * (128 + 128) * 32 * 4;  // 98304 bytes

// ---------------------------------------------------------------- V transpose
// Vt[d][n] = tf32_round(V[n][d]);  V:[NKc][Dc] -> Vt:[Dc][NKc]
__global__ __launch_bounds__(256)
void transpose_kernel(const float* __restrict__ V, float* __restrict__ Vt)
{
    __shared__ float tile[32][33];
    const int d0 = blockIdx.x * 32;
    const int n0 = blockIdx.y * 32;
    const int tx = threadIdx.x, ty = threadIdx.y;
#pragma unroll
    for (int j = 0; j < 32; j += 8)
        tile[ty + j][tx] = V[(size_t)(n0 + ty + j) * Dc + d0 + tx];
    __syncthreads();
#pragma unroll
    for (int j = 0; j < 32; j += 8)
        Vt[(size_t)(d0 + ty + j) * NKc + n0 + tx] = f2tf_f(tile[tx][ty + j]);
}

// ---------------------------------------------------------------- softmax
// In-place row softmax; stores tf32-rounded P so the P@V GEMM is exact.
__global__ __launch_bounds__(256)
void softmax_kernel(float* __restrict__ S)
{
    __shared__ float red[256];
    const int row = blockIdx.x;
    const int t = threadIdx.x;
    float* p = S + (size_t)row * NKc;

    float v[32];
    float mx = -3.4e38f;
#pragma unroll
    for (int i = 0; i < 32; i++) {
        v[i] = p[i * 256 + t];
        mx = fmaxf(mx, v[i]);
    }
    red[t] = mx;
    __syncthreads();
    for (int s = 128; s > 0; s >>= 1) {
        if (t < s) red[t] = fmaxf(red[t], red[t + s]);
        __syncthreads();
    }
    mx = red[0];
    __syncthreads();

    float sum = 0.0f;
#pragma unroll
    for (int i = 0; i < 32; i++) {
        v[i] = expf(v[i] - mx);
        sum += v[i];
    }
    red[t] = sum;
    __syncthreads();
    for (int s = 128; s > 0; s >>= 1) {
        if (t < s) red[t] += red[t + s];
        __syncthreads();
    }
    const float inv = 1.0f / red[0];
#pragma unroll
    for (int i = 0; i < 32; i++) p[i * 256 + t] = f2tf_f(v[i] * inv);
}

// ---------------------------------------------------------------- launcher
extern "C" void kernel_launch(void* const* d_in, const int* in_sizes, int n_in,
                              void* d_out, int out_size)
{
    (void)in_sizes; (void)n_in; (void)out_size;
    const float* Q    = (const float*)d_in[0];
    const float* K    = (const float*)d_in[1];
    const float* V    = (const float*)d_in[2];
    const float* WQw  = (const float*)d_in[3];
    const float* WQb  = (const float*)d_in[4];
    const float* WKw  = (const float*)d_in[5];
    const float* WKb  = (const float*)d_in[6];
    const int*   mask = (const int*)d_in[7];  // numpy bool -> int32 on device
    float* O = (float*)d_out;

    float *Qp, *Kp, *Vt, *S;
    cudaGetSymbolAddress((void**)&Qp, g_Qp);
    cudaGetSymbolAddress((void**)&Kp, g_Kp);
    cudaGetSymbolAddress((void**)&Vt, g_Vt);
    cudaGetSymbolAddress((void**)&S,  g_S);

    cudaFuncSetAttribute(mma_gemm<EPI_BIAS>,
                         cudaFuncAttributeMaxDynamicSharedMemorySize, GEMM_SMEM);
    cudaFuncSetAttribute(mma_gemm<EPI_MASK>,
                         cudaFuncAttributeMaxDynamicSharedMemorySize, GEMM_SMEM);
    cudaFuncSetAttribute(mma_gemm<EPI_NONE>,
                         cudaFuncAttributeMaxDynamicSharedMemorySize, GEMM_SMEM);

    const dim3 blk(256);

    // 0) Vt = tf32(V^T)   [512 x 8192]
    transpose_kernel<<<dim3(Dc / 32, NKc / 32), dim3(32, 8)>>>(V, Vt);

    // 1) Projections: Qp = tf32(Q @ WQw^T + WQb) ; Kp = tf32(K @ WKw^T + WKb)
    {
        dim3 grid(Dc / 128, NQc / 128);
        mma_gemm<EPI_BIAS><<<grid, blk, GEMM_SMEM>>>(Q, WQw, Qp, WQb, nullptr, NQc, Dc, Dc);
        mma_gemm<EPI_BIAS><<<grid, blk, GEMM_SMEM>>>(K, WKw, Kp, WKb, nullptr, NKc, Dc, Dc);
    }
    // 2) S = mask ? NEG : (Qp @ Kp^T) * (1/sqrt(512))   [8192 x 8192]
    {
        dim3 grid(NKc / 128, NQc / 128);
        mma_gemm<EPI_MASK><<<grid, blk, GEMM_SMEM>>>(Qp, Kp, S, nullptr, mask, NQc, NKc, Dc);
    }
    // 3) P = tf32(softmax_rows(S)), in place
    softmax_kernel<<<NQc, blk>>>(S);
    // 4) O = P @ V = P @ Vt^T   [8192 x 512]
    {
        dim3 grid(Dc / 128, NQc / 128);
        mma_gemm<EPI_NONE><<<grid, blk, GEMM_SMEM>>>(S, Vt, O, nullptr, nullptr, NQc, Dc, NKc);
    }
}

// round 9
// speedup vs baseline: 4.1990x; 1.1107x over previous
#include <cuda_runtime.h>
#include <cstdint>

// Problem constants (fixed shapes from reference)
#define NQc 8192
#define NKc 8192
#define Dc  512

__device__ __align__(16) float g_Qp[(size_t)NQc * Dc];
__device__ __align__(16) float g_Kp[(size_t)NKc * Dc];
__device__ __align__(16) float g_Vt[(size_t)Dc * NKc];
__device__ __align__(16) float g_S [(size_t)NQc * NKc];

static constexpr float SCALE_P = 0.044194173824159216f; // 1/sqrt(512)
static constexpr float NEGV    = -4294967296.0f;        // -(1<<32)

enum { EPI_NONE = 0, EPI_BIAS = 1, EPI_MASK = 2 };

// fp32 -> tf32 (round-to-nearest) kept in a 32-bit container (low 13 bits zero)
__device__ __forceinline__ uint32_t f2tf(float f) {
    uint32_t r;
    asm("cvt.rna.tf32.f32 %0, %1;" : "=r"(r) : "f"(f));
    return r;
}
__device__ __forceinline__ float f2tf_f(float f) { return __uint_as_float(f2tf(f)); }

__device__ __forceinline__ uint32_t smem_u32(const void* p) {
    uint32_t r;
    asm("{ .reg .u64 t; cvta.to.shared.u64 t, %1; cvt.u32.u64 %0, t; }"
        : "=r"(r) : "l"(p));
    return r;
}

#define CP_ASYNC16(dst, src) \
    asm volatile("cp.async.cg.shared.global [%0], [%1], 16;" \
                 :: "r"(dst), "l"(src) : "memory")
#define CP_COMMIT() asm volatile("cp.async.commit_group;" ::: "memory")
#define CP_WAIT(N)  asm volatile("cp.async.wait_group %0;" :: "n"(N) : "memory")

#define LDSM_X4(r, addr) \
    asm volatile("ldmatrix.sync.aligned.m8n8.x4.shared.b16 {%0,%1,%2,%3}, [%4];" \
                 : "=r"((r)[0]), "=r"((r)[1]), "=r"((r)[2]), "=r"((r)[3]) \
                 : "r"(addr))

__device__ __forceinline__ void mma8(float* c, const uint32_t* a, const uint32_t* b) {
    asm volatile(
        "mma.sync.aligned.m16n8k8.row.col.f32.tf32.tf32.f32 "
        "{%0,%1,%2,%3}, {%4,%5,%6,%7}, {%8,%9}, {%0,%1,%2,%3};"
        : "+f"(c[0]), "+f"(c[1]), "+f"(c[2]), "+f"(c[3])
        : "r"(a[0]), "r"(a[1]), "r"(a[2]), "r"(a[3]), "r"(b[0]), "r"(b[1]));
}

// ---------------------------------------------------------------- mma GEMM
// C[M,N] = A[M,K] @ B^T, A:[M,K], B:[N,K], all K-major.
// BM=128, BN=128, BK=32; 256 threads = 8 warps (2 M x 4 N), warp tile 64x32.
// 3-stage cp.async pipeline. Smem tiles [row][32] with XOR swizzle on the
// float4 column (col4' = col4 ^ (row&7)): cp.async dst conflict-free, and
// all fragments loaded via ldmatrix.x4 (tf32 8x4 block == 8x8 b16 matrix),
// 6 LDSM per k-step instead of 24 LDS.32.
// NOTE: MMA reads raw fp32 bits as tf32 (truncation). For exact tf32 math,
// A/B must be pre-rounded to tf32 in gmem (true for Qp, Kp, P, Vt).
// Requires M%128==0, N%128==0, K%96==0 or KC>=3 handled (KC>=2 ok).
template <int EPI>
__global__ void __launch_bounds__(256, 2)
mma_gemm(const float* __restrict__ A, const float* __restrict__ B,
         float* __restrict__ C, const float* __restrict__ bias,
         const int* __restrict__ mask, int M, int N, int K)
{
    constexpr int BM = 128, BN = 128, BK = 32, STAGES = 3;
    constexpr int STAGE_F = (BM + BN) * BK;       // floats per stage (8192)
    constexpr int STAGE_B = STAGE_F * 4;          // bytes (32768)
    constexpr int ABYTES  = BM * BK * 4;          // 16384

    extern __shared__ float sm[];
    const uint32_t smb = smem_u32(sm);

    const int tid  = threadIdx.x;
    const int lane = tid & 31;
    const int wid  = tid >> 5;
    const int g    = lane >> 2;     // group id 0..7
    const int t    = lane & 3;      // thread-in-group 0..3

    const int m_warp = (wid & 1) * 64;   // 2 warps in M
    const int n_warp = (wid >> 1) * 32;  // 4 warps in N

    const int rowBase = blockIdx.y * BM;
    const int colBase = blockIdx.x * BN;

    // ---- ldmatrix per-lane addressing
    // x4 matrices: lanes l -> matrix l>>3, row-in-matrix l&7.
    const int mat = lane >> 3;
    const int rim = lane & 7;
    const int km  = mat >> 1;   // A: k-half select, B: n-half select
    const int kb  = mat & 1;    // A: +8 row select, B: k-half select
    // A fragment (mi, ks): row = m_warp + 16*mi + rim + 8*kb, col4 = 2*ks + km
    // B fragment (j,  ks): row = n_warp + 16*j  + rim + 8*km, col4 = 2*ks + kb
    // (row & 7) == rim for both.
    const uint32_t aOff = (uint32_t)(m_warp + rim + 8 * kb) * (BK * 4);
    const uint32_t bOff = ABYTES + (uint32_t)(n_warp + rim + 8 * km) * (BK * 4);

    // loader mapping: rows lr+32*it, float4 col lq, swizzled col sq
    const int lr = tid >> 3;
    const int lq = tid & 7;
    const int sq = lq ^ (lr & 7);

    const float* pa = A + (size_t)(rowBase + lr) * K + lq * 4;
    const float* pb = B + (size_t)(colBase + lr) * K + lq * 4;
    const uint32_t sa = smb + (uint32_t)(lr * BK + 4 * sq) * 4;
    const uint32_t sb = sa + (uint32_t)ABYTES;

    const int KC = K / BK;

    // issue one stage of cp.async (8 x 16B per thread)
    auto issue = [&](int c, int s) {
        const float* qa = pa + (size_t)c * BK;
        const float* qb = pb + (size_t)c * BK;
        const uint32_t off = (uint32_t)s * STAGE_B;
#pragma unroll
        for (int it = 0; it < 4; it++) {
            CP_ASYNC16(sa + off + (uint32_t)(32 * it * BK) * 4, qa + (size_t)(32 * it) * K);
            CP_ASYNC16(sb + off + (uint32_t)(32 * it * BK) * 4, qb + (size_t)(32 * it) * K);
        }
        CP_COMMIT();
    };

    issue(0, 0);
    issue(1, 1);

    float acc[4][4][4];
#pragma unroll
    for (int i = 0; i < 4; i++)
#pragma unroll
        for (int j = 0; j < 4; j++)
#pragma unroll
            for (int r = 0; r < 4; r++) acc[i][j][r] = 0.0f;

    for (int c = 0; c < KC; c++) {
        if (c + 2 < KC) { CP_WAIT(1); } else { CP_WAIT(0); }
        __syncthreads();

        if (c + 2 < KC) issue(c + 2, (c + 2) % STAGES);

        const uint32_t stg = smb + (uint32_t)(c % STAGES) * STAGE_B;
#pragma unroll
        for (int ks = 0; ks < 4; ks++) {
            const uint32_t cA = 16u * (uint32_t)((2 * ks + km) ^ rim);
            const uint32_t cB = 16u * (uint32_t)((2 * ks + kb) ^ rim);
            uint32_t af[4][4];
#pragma unroll
            for (int mi = 0; mi < 4; mi++)
                LDSM_X4(af[mi], stg + aOff + (uint32_t)(mi * 16 * BK * 4) + cA);
            uint32_t bf[2][4];   // [j] = {b0(nj=2j), b1(2j), b0(2j+1), b1(2j+1)}
#pragma unroll
            for (int j = 0; j < 2; j++)
                LDSM_X4(bf[j], stg + bOff + (uint32_t)(j * 16 * BK * 4) + cB);
#pragma unroll
            for (int mi = 0; mi < 4; mi++)
#pragma unroll
                for (int nj = 0; nj < 4; nj++)
                    mma8(acc[mi][nj], af[mi], &bf[nj >> 1][(nj & 1) * 2]);
        }
        __syncthreads();
    }

    // ---- epilogue
    const int colW = colBase + n_warp;
#pragma unroll
    for (int mi = 0; mi < 4; mi++) {
        const int row0 = rowBase + m_warp + 16 * mi + g;
#pragma unroll
        for (int rr = 0; rr < 2; rr++) {
            const int row = row0 + 8 * rr;
            float* crow = C + (size_t)row * N;
            const int* mrow = (EPI == EPI_MASK) ? (mask + (size_t)row * N) : nullptr;
#pragma unroll
            for (int nj = 0; nj < 4; nj++) {
                const int col = colW + 8 * nj + 2 * t;
                float2 o = make_float2(acc[mi][nj][2 * rr], acc[mi][nj][2 * rr + 1]);
                if (EPI == EPI_BIAS) {
                    const float2 b = *(const float2*)(bias + col);
                    // round to tf32 so downstream cp.async GEMM is exact
                    o.x = f2tf_f(o.x + b.x);
                    o.y = f2tf_f(o.y + b.y);
                } else if (EPI == EPI_MASK) {
                    const int2 m = *(const int2*)(mrow + col);
                    o.x = m.x ? NEGV : o.x * SCALE_P;
                    o.y = m.y ? NEGV : o.y * SCALE_P;
                }
                *(float2*)(crow + col) = o;
            }
        }
    }
}

static constexpr int GEMM_SMEM = 3 * (128 + 128) * 32 * 4;  // 98304 bytes

// ---------------------------------------------------------------- V transpose
// Vt[d][n] = tf32_round(V[n][d]);  V:[NKc][Dc] -> Vt:[Dc][NKc]
__global__ __launch_bounds__(256)
void transpose_kernel(const float* __restrict__ V, float* __restrict__ Vt)
{
    __shared__ float tile[32][33];
    const int d0 = blockIdx.x * 32;
    const int n0 = blockIdx.y * 32;
    const int tx = threadIdx.x, ty = threadIdx.y;
#pragma unroll
    for (int j = 0; j < 32; j += 8)
        tile[ty + j][tx] = V[(size_t)(n0 + ty + j) * Dc + d0 + tx];
    __syncthreads();
#pragma unroll
    for (int j = 0; j < 32; j += 8)
        Vt[(size_t)(d0 + ty + j) * NKc + n0 + tx] = f2tf_f(tile[tx][ty + j]);
}

// ---------------------------------------------------------------- softmax
// In-place row softmax; stores tf32-rounded P so the P@V GEMM is exact.
__global__ __launch_bounds__(256)
void softmax_kernel(float* __restrict__ S)
{
    __shared__ float red[256];
    const int row = blockIdx.x;
    const int t = threadIdx.x;
    float* p = S + (size_t)row * NKc;

    float v[32];
    float mx = -3.4e38f;
#pragma unroll
    for (int i = 0; i < 32; i++) {
        v[i] = p[i * 256 + t];
        mx = fmaxf(mx, v[i]);
    }
    red[t] = mx;
    __syncthreads();
    for (int s = 128; s > 0; s >>= 1) {
        if (t < s) red[t] = fmaxf(red[t], red[t + s]);
        __syncthreads();
    }
    mx = red[0];
    __syncthreads();

    float sum = 0.0f;
#pragma unroll
    for (int i = 0; i < 32; i++) {
        v[i] = expf(v[i] - mx);
        sum += v[i];
    }
    red[t] = sum;
    __syncthreads();
    for (int s = 128; s > 0; s >>= 1) {
        if (t < s) red[t] += red[t + s];
        __syncthreads();
    }
    const float inv = 1.0f / red[0];
#pragma unroll
    for (int i = 0; i < 32; i++) p[i * 256 + t] = f2tf_f(v[i] * inv);
}

// ---------------------------------------------------------------- launcher
extern "C" void kernel_launch(void* const* d_in, const int* in_sizes, int n_in,
                              void* d_out, int out_size)
{
    (void)in_sizes; (void)n_in; (void)out_size;
    const float* Q    = (const float*)d_in[0];
    const float* K    = (const float*)d_in[1];
    const float* V    = (const float*)d_in[2];
    const float* WQw  = (const float*)d_in[3];
    const float* WQb  = (const float*)d_in[4];
    const float* WKw  = (const float*)d_in[5];
    const float* WKb  = (const float*)d_in[6];
    const int*   mask = (const int*)d_in[7];  // numpy bool -> int32 on device
    float* O = (float*)d_out;

    float *Qp, *Kp, *Vt, *S;
    cudaGetSymbolAddress((void**)&Qp, g_Qp);
    cudaGetSymbolAddress((void**)&Kp, g_Kp);
    cudaGetSymbolAddress((void**)&Vt, g_Vt);
    cudaGetSymbolAddress((void**)&S,  g_S);

    cudaFuncSetAttribute(mma_gemm<EPI_BIAS>,
                         cudaFuncAttributeMaxDynamicSharedMemorySize, GEMM_SMEM);
    cudaFuncSetAttribute(mma_gemm<EPI_MASK>,
                         cudaFuncAttributeMaxDynamicSharedMemorySize, GEMM_SMEM);
    cudaFuncSetAttribute(mma_gemm<EPI_NONE>,
                         cudaFuncAttributeMaxDynamicSharedMemorySize, GEMM_SMEM);

    const dim3 blk(256);

    // 0) Vt = tf32(V^T)   [512 x 8192]
    transpose_kernel<<<dim3(Dc / 32, NKc / 32), dim3(32, 8)>>>(V, Vt);

    // 1) Projections: Qp = tf32(Q @ WQw^T + WQb) ; Kp = tf32(K @ WKw^T + WKb)
    {
        dim3 grid(Dc / 128, NQc / 128);
        mma_gemm<EPI_BIAS><<<grid, blk, GEMM_SMEM>>>(Q, WQw, Qp, WQb, nullptr, NQc, Dc, Dc);
        mma_gemm<EPI_BIAS><<<grid, blk, GEMM_SMEM>>>(K, WKw, Kp, WKb, nullptr, NKc, Dc, Dc);
    }
    // 2) S = mask ? NEG : (Qp @ Kp^T) * (1/sqrt(512))   [8192 x 8192]
    {
        dim3 grid(NKc / 128, NQc / 128);
        mma_gemm<EPI_MASK><<<grid, blk, GEMM_SMEM>>>(Qp, Kp, S, nullptr, mask, NQc, NKc, Dc);
    }
    // 3) P = tf32(softmax_rows(S)), in place
    softmax_kernel<<<NQc, blk>>>(S);
    // 4) O = P @ V = P @ Vt^T   [8192 x 512]
    {
        dim3 grid(Dc / 128, NQc / 128);
        mma_gemm<EPI_NONE><<<grid, blk, GEMM_SMEM>>>(S, Vt, O, nullptr, nullptr, NQc, Dc, NKc);
    }
}